// round 4
// baseline (speedup 1.0000x reference)
#include <cuda_runtime.h>
#include <cuda_fp16.h>
#include <cstdint>

// Problem constants
#define KVC   512
#define NH    16
#define HD    64
#define HWSZ  4096
#define NB    32
#define MTOT  (NB*HWSZ)     // 131072 pixels
#define NVAL  1024          // NH*HD value columns

// value-kernel tiles (fp16 mma)
#define BM      128
#define BN      256
#define BK      32
#define NCHUNK  (KVC/BK)    // 16
#define ROWB    80          // padded row stride bytes (32 fp16 = 64B + 16B pad)
#define A_BYTES (BM*ROWB)              // 10240
#define STAGE_B ((BM+BN)*ROWB)         // 30720
#define OFF_RED (3*STAGE_B)            // red[8][64] floats = 2048 B
#define OFF_BV  (OFF_RED + 8*64*4)     // bv tile [256] = 1024 B
#define SMEMB   (OFF_BV + BN*4)

// ---------------- device scratch ----------------
__device__ __align__(16) float g_Wq[KVC*NH];
__device__ float g_qb[NH];
__device__ float g_logits[(size_t)(NB*NH)*HWSZ];      // [b*16+n][s], 8 MiB
__device__ float g_mx[NB*NH];
__device__ float g_inv[NB*NH];
__device__ __align__(16) float g_partial[(size_t)(MTOT/BM)*NVAL];
__device__ __align__(16) __half g_xh[(size_t)MTOT*KVC];     // x in fp16, 128 MiB
__device__ __align__(16) __half g_WvTh[(size_t)NVAL*KVC];   // Wv^T fp16 [n][k]

// ---------------- helpers ----------------
__device__ __forceinline__ float cvt_tf32(float x){
    float r; asm("cvt.rna.tf32.f32 %0, %1;" : "=f"(r) : "f"(x)); return r;
}
__device__ __forceinline__ uint32_t smem_u32(const void* p){
    uint32_t a;
    asm("{ .reg .u64 t; cvta.to.shared.u64 t, %1; cvt.u32.u64 %0, t; }" : "=r"(a) : "l"(p));
    return a;
}
__device__ __forceinline__ void cp16(uint32_t dst, const void* src){
    asm volatile("cp.async.cg.shared.global [%0], [%1], 16;" :: "r"(dst), "l"(src) : "memory");
}
__device__ __forceinline__ void ldm_x4(uint32_t a, uint32_t r[4]){
    asm volatile("ldmatrix.sync.aligned.m8n8.x4.shared.b16 {%0,%1,%2,%3}, [%4];"
                 : "=r"(r[0]), "=r"(r[1]), "=r"(r[2]), "=r"(r[3]) : "r"(a));
}
__device__ __forceinline__ void mma_f16(float c[4], const uint32_t a[4],
                                        uint32_t b0, uint32_t b1){
    asm volatile(
        "mma.sync.aligned.m16n8k16.row.col.f32.f16.f16.f32 "
        "{%0,%1,%2,%3},{%4,%5,%6,%7},{%8,%9},{%0,%1,%2,%3};\n"
        : "+f"(c[0]), "+f"(c[1]), "+f"(c[2]), "+f"(c[3])
        : "r"(a[0]), "r"(a[1]), "r"(a[2]), "r"(a[3]), "r"(b0), "r"(b1));
}
// m16n8k8 tf32 for the small logits GEMM
__device__ __forceinline__ void mma_tf32(float c[4],
                                         uint32_t a0, uint32_t a1, uint32_t a2, uint32_t a3,
                                         uint32_t b0, uint32_t b1){
    asm volatile(
        "mma.sync.aligned.m16n8k8.row.col.f32.tf32.tf32.f32 "
        "{%0,%1,%2,%3},{%4,%5,%6,%7},{%8,%9},{%0,%1,%2,%3};\n"
        : "+f"(c[0]), "+f"(c[1]), "+f"(c[2]), "+f"(c[3])
        : "r"(a0), "r"(a1), "r"(a2), "r"(a3), "r"(b0), "r"(b1));
}
__device__ __forceinline__ float fast_tanh(float x){
    x = fminf(fmaxf(x, -15.f), 15.f);
    float e = __expf(2.0f * x);
    return __fdividef(e - 1.0f, e + 1.0f);
}

// ---------------- kernel 0: transpose+convert Wv [512,1024] -> g_WvTh [1024,512] ----
__global__ void transpose_wv(const float* __restrict__ Wv){
    __shared__ float t[32][33];
    int n0 = blockIdx.x * 32, k0 = blockIdx.y * 32;
    int tx = threadIdx.x, ty = threadIdx.y;           // 32 x 8
    #pragma unroll
    for (int i = 0; i < 4; i++)
        t[ty + 8*i][tx] = Wv[(size_t)(k0 + ty + 8*i)*NVAL + n0 + tx];
    __syncthreads();
    #pragma unroll
    for (int i = 0; i < 4; i++)
        g_WvTh[(size_t)(n0 + ty + 8*i)*KVC + k0 + tx] = __float2half_rn(t[tx][ty + 8*i]);
}

// ---------------- kernel 1: fold query into W_k / b_k ----------------
__global__ void fold_q(const float* __restrict__ Wk, const float* __restrict__ bk,
                       const float* __restrict__ q){
    int n = blockIdx.x;
    __shared__ float qs[HD];
    if (threadIdx.x < HD) qs[threadIdx.x] = q[n*HD + threadIdx.x];
    __syncthreads();
    for (int c = threadIdx.x; c < KVC; c += blockDim.x){
        float s = 0.f;
        #pragma unroll 8
        for (int d = 0; d < HD; d++) s += Wk[(size_t)c*NVAL + n*HD + d] * qs[d];
        g_Wq[c*NH + n] = s;
    }
    if (threadIdx.x == 0){
        float s = 0.f;
        for (int d = 0; d < HD; d++) s += bk[n*HD + d] * qs[d];
        g_qb[n] = s;
    }
}

// ---------------- kernel 2: logits GEMM + x->fp16 conversion ----------------
__global__ __launch_bounds__(256) void logits_gemm(const float* __restrict__ x){
    __shared__ float As[128][68];
    __shared__ float Bs[64][24];
    int tid  = threadIdx.x;
    int wid  = tid >> 5, lane = tid & 31;
    int g    = lane >> 2, tq = lane & 3;
    int bm0  = blockIdx.x * 128;

    float acc[2][4] = {};

    for (int kt = 0; kt < KVC/64; kt++){
        int k0 = kt * 64;
        #pragma unroll
        for (int i = 0; i < 8; i++){
            int idx = tid + 256*i;
            int row = idx >> 4, c4 = (idx & 15) * 4;
            float4 v = *reinterpret_cast<const float4*>(x + (size_t)(bm0+row)*KVC + k0 + c4);
            __half2 h0 = __floats2half2_rn(v.x, v.y);
            __half2 h1 = __floats2half2_rn(v.z, v.w);
            uint2 u;
            u.x = *reinterpret_cast<uint32_t*>(&h0);
            u.y = *reinterpret_cast<uint32_t*>(&h1);
            *reinterpret_cast<uint2*>(&g_xh[(size_t)(bm0+row)*KVC + k0 + c4]) = u;
            float* d = &As[row][c4];
            d[0]=cvt_tf32(v.x); d[1]=cvt_tf32(v.y); d[2]=cvt_tf32(v.z); d[3]=cvt_tf32(v.w);
        }
        {
            int k = tid >> 2, n4 = (tid & 3) * 4;
            float4 v = *reinterpret_cast<const float4*>(g_Wq + (k0+k)*NH + n4);
            float* d = &Bs[k][n4];
            d[0]=cvt_tf32(v.x); d[1]=cvt_tf32(v.y); d[2]=cvt_tf32(v.z); d[3]=cvt_tf32(v.w);
        }
        __syncthreads();
        #pragma unroll
        for (int ks = 0; ks < 8; ks++){
            int m = wid*16 + g;
            uint32_t a0 = __float_as_uint(As[m    ][ks*8 + tq    ]);
            uint32_t a1 = __float_as_uint(As[m + 8][ks*8 + tq    ]);
            uint32_t a2 = __float_as_uint(As[m    ][ks*8 + tq + 4]);
            uint32_t a3 = __float_as_uint(As[m + 8][ks*8 + tq + 4]);
            #pragma unroll
            for (int ni = 0; ni < 2; ni++){
                uint32_t b0 = __float_as_uint(Bs[ks*8 + tq    ][ni*8 + g]);
                uint32_t b1 = __float_as_uint(Bs[ks*8 + tq + 4][ni*8 + g]);
                mma_tf32(acc[ni], a0,a1,a2,a3, b0,b1);
            }
        }
        __syncthreads();
    }
    #pragma unroll
    for (int ni = 0; ni < 2; ni++){
        #pragma unroll
        for (int r = 0; r < 4; r++){
            int row  = bm0 + wid*16 + g + ((r >= 2) ? 8 : 0);
            int head = ni*8 + 2*tq + (r & 1);
            int b = row >> 12, s = row & 4095;
            g_logits[(size_t)(b*NH + head)*HWSZ + s] = acc[ni][r] + g_qb[head];
        }
    }
}

// ---------------- kernel 3: softmax stats ----------------
__global__ void softmax_stats(){
    __shared__ float sm[256];
    int row = blockIdx.x, tid = threadIdx.x;
    const float* lp = g_logits + (size_t)row * HWSZ;
    float m = -1e30f;
    for (int i = tid; i < HWSZ; i += 256) m = fmaxf(m, lp[i]);
    sm[tid] = m; __syncthreads();
    for (int o = 128; o > 0; o >>= 1){
        if (tid < o) sm[tid] = fmaxf(sm[tid], sm[tid+o]);
        __syncthreads();
    }
    float mrow = sm[0];
    __syncthreads();
    float s = 0.f;
    for (int i = tid; i < HWSZ; i += 256) s += __expf(lp[i] - mrow);
    sm[tid] = s; __syncthreads();
    for (int o = 128; o > 0; o >>= 1){
        if (tid < o) sm[tid] += sm[tid+o];
        __syncthreads();
    }
    if (tid == 0){ g_mx[row] = mrow; g_inv[row] = 1.0f / sm[0]; }
}

// ---------------- kernel 4: fp16 value GEMM + fused epilogue ----------
// BM=128 x BN=256 tile, 8 warps, warp tile 64x64, 3-stage cp.async pipeline
__global__ void __launch_bounds__(256, 1) value_f16(const float* __restrict__ bv){
    extern __shared__ char smc[];
    float* smf = (float*)smc;
    uint32_t sb = smem_u32(smc);
    int tid = threadIdx.x;
    int wid = tid >> 5, lane = tid & 31;
    int wm  = wid >> 2, wn = wid & 3;       // 2 x 4 warp grid, warp tile 64x64
    int bn0 = blockIdx.x * BN;
    int mt  = blockIdx.y;
    int bm0 = mt * BM;
    int g   = lane >> 2, tq = lane & 3;

    if (tid < BN) smf[(OFF_BV>>2) + tid] = bv[bn0 + tid];

    // precompute softmax weights for this thread's 8 accumulator rows
    int head = (bn0 + wn*64) >> 6;          // warp's 64 cols = exactly one head
    float wgt[8];
    #pragma unroll
    for (int mi = 0; mi < 4; mi++){
        #pragma unroll
        for (int rg = 0; rg < 2; rg++){
            int p  = bm0 + wm*64 + mi*16 + g + rg*8;
            int b  = p >> 12, s = p & 4095;
            int bh = b*NH + head;
            wgt[mi*2+rg] = __expf(g_logits[((size_t)bh << 12) + s] - g_mx[bh]) * g_inv[bh];
        }
    }

    // cp.async mapping
    int lmA = tid >> 1, lgA = (tid & 1) * 2;        // A: 2 granules/thread
    const __half* srcA = g_xh   + (size_t)(bm0 + lmA)*KVC + lgA*8;
    const __half* srcB = g_WvTh + (size_t)(bn0 + tid)*KVC;   // B: 4 granules/thread
    uint32_t dstA = sb + lmA*ROWB + lgA*16;
    uint32_t dstB = sb + A_BYTES + tid*ROWB;

    #define LOAD_STAGE(kt) do{ \
        uint32_t so = (uint32_t)((kt) % 3) * STAGE_B; \
        int ko = (kt) * BK; \
        cp16(dstA + so,      srcA + ko); \
        cp16(dstA + so + 16, srcA + ko + 8); \
        cp16(dstB + so,      srcB + ko); \
        cp16(dstB + so + 16, srcB + ko + 8); \
        cp16(dstB + so + 32, srcB + ko + 16); \
        cp16(dstB + so + 48, srcB + ko + 24); \
    } while(0)

    LOAD_STAGE(0);
    asm volatile("cp.async.commit_group;" ::: "memory");
    LOAD_STAGE(1);
    asm volatile("cp.async.commit_group;" ::: "memory");

    float acc[4][8][4] = {};                 // [mi][ni][r]
    int lrow = lane & 15, lhi = lane >> 4;

    for (int kt = 0; kt < NCHUNK; kt++){
        asm volatile("cp.async.wait_group 1;" ::: "memory");
        __syncthreads();
        if (kt + 2 < NCHUNK) LOAD_STAGE(kt + 2);
        asm volatile("cp.async.commit_group;" ::: "memory");

        uint32_t so = (uint32_t)(kt % 3) * STAGE_B;
        uint32_t Ab = sb + so + (wm*64 + lrow)*ROWB;
        uint32_t Bb = sb + so + A_BYTES + (wn*64 + lrow)*ROWB;

        #pragma unroll
        for (int ks = 0; ks < 2; ks++){
            uint32_t gsel = (ks*2 + lhi) * 16;
            uint32_t a[4][4];
            #pragma unroll
            for (int mi = 0; mi < 4; mi++)
                ldm_x4(Ab + mi*16*ROWB + gsel, a[mi]);
            uint32_t b[8][2];
            #pragma unroll
            for (int np = 0; np < 4; np++){
                uint32_t r[4];
                ldm_x4(Bb + np*16*ROWB + gsel, r);
                b[2*np  ][0] = r[0]; b[2*np  ][1] = r[2];
                b[2*np+1][0] = r[1]; b[2*np+1][1] = r[3];
            }
            #pragma unroll
            for (int mi = 0; mi < 4; mi++)
                #pragma unroll
                for (int ni = 0; ni < 8; ni++)
                    mma_f16(acc[mi][ni], a[mi], b[ni][0], b[ni][1]);
        }
    }

    // ---- epilogue: tanh + attention weight + reduce over 128 tile rows ----
    float* bvs = smf + (OFF_BV >> 2);
    float colsum[16] = {};
    #pragma unroll
    for (int mi = 0; mi < 4; mi++){
        #pragma unroll
        for (int rg = 0; rg < 2; rg++){
            float w = wgt[mi*2+rg];
            #pragma unroll
            for (int ni = 0; ni < 8; ni++){
                #pragma unroll
                for (int c01 = 0; c01 < 2; c01++){
                    int j = wn*64 + ni*8 + 2*tq + c01;
                    float t = fast_tanh(acc[mi][ni][rg*2 + c01] + bvs[j]);
                    colsum[ni*2 + c01] += w * t;
                }
            }
        }
    }
    #pragma unroll
    for (int i = 0; i < 16; i++){
        colsum[i] += __shfl_xor_sync(0xffffffffu, colsum[i], 16);
        colsum[i] += __shfl_xor_sync(0xffffffffu, colsum[i], 8);
        colsum[i] += __shfl_xor_sync(0xffffffffu, colsum[i], 4);
    }
    float* red = smf + (OFF_RED >> 2);       // [8 warps][64 cols]
    if (lane < 4){
        #pragma unroll
        for (int ni = 0; ni < 8; ni++)
            #pragma unroll
            for (int c01 = 0; c01 < 2; c01++)
                red[wid*64 + ni*8 + 2*tq + c01] = colsum[ni*2 + c01];
    }
    __syncthreads();
    {
        int wn2 = tid >> 6, cl = tid & 63;
        float v = red[wn2*64 + cl] + red[(4 + wn2)*64 + cl];
        g_partial[(size_t)mt*NVAL + bn0 + tid] = v;   // unique writer -> deterministic
    }
}

// ---------------- kernel 5: reduce partials ----------------
__global__ void reduce_out(float* __restrict__ out){
    int o = blockIdx.x * 256 + threadIdx.x;   // 32768 outputs [b][n][v]
    int b = o >> 10, j = o & 1023;
    float s = 0.f;
    #pragma unroll
    for (int i = 0; i < 32; i++)
        s += g_partial[(size_t)(b*32 + i)*NVAL + j];
    out[o] = s;
}

// ---------------- launch ----------------
extern "C" void kernel_launch(void* const* d_in, const int* in_sizes, int n_in,
                              void* d_out, int out_size){
    const float* kv = (const float*)d_in[0];
    const float* Wk = (const float*)d_in[1];
    const float* bk = (const float*)d_in[2];
    const float* Wv = (const float*)d_in[3];
    const float* bv = (const float*)d_in[4];
    const float* q  = (const float*)d_in[5];
    float* out = (float*)d_out;

    static bool attr_done = false;
    if (!attr_done){
        cudaFuncSetAttribute(value_f16, cudaFuncAttributeMaxDynamicSharedMemorySize, SMEMB);
        attr_done = true;
    }

    transpose_wv<<<dim3(NVAL/32, KVC/32), dim3(32, 8)>>>(Wv);
    fold_q<<<NH, 128>>>(Wk, bk, q);
    logits_gemm<<<MTOT/128, 256>>>(kv);
    softmax_stats<<<NB*NH, 256>>>();
    value_f16<<<dim3(NVAL/BN, MTOT/BM), 256, SMEMB>>>(bv);
    reduce_out<<<(NB*NVAL)/256, 256>>>(out);
}

// round 6
// speedup vs baseline: 1.1089x; 1.1089x over previous
#include <cuda_runtime.h>
#include <cuda_fp16.h>
#include <cstdint>

// Problem constants
#define KVC   512
#define NH    16
#define HD    64
#define HWSZ  4096
#define NB    32
#define MTOT  (NB*HWSZ)     // 131072 pixels
#define NVAL  1024          // NH*HD value columns

// value-kernel tiles (fp16 mma)
#define BM      128
#define BN      128
#define BK      64
#define NCHUNK  (KVC/BK)    // 8
#define ROWB    144         // 64 fp16 = 128B + 16B pad (conflict-free ldmatrix)
#define A_BYTES (BM*ROWB)              // 18432
#define STAGE_B ((BM+BN)*ROWB)         // 36864
#define OFF_RED (3*STAGE_B)            // red[8][32] floats = 1024 B
#define OFF_BV  (OFF_RED + 1024)       // bv tile [128] = 512 B
#define SMEMB   (OFF_BV + BN*4)        // 112128 B -> 2 CTAs/SM

// ---------------- device scratch ----------------
__device__ __align__(16) float g_Wq[KVC*NH];
__device__ float g_qb[NH];
__device__ float g_logits[(size_t)(NB*NH)*HWSZ];      // [b*16+n][s], 8 MiB
__device__ float g_mx[NB*NH];
__device__ float g_inv[NB*NH];
__device__ __align__(16) float g_partial[(size_t)(MTOT/BM)*NVAL];
__device__ __align__(16) __half g_xh[(size_t)MTOT*KVC];     // x in fp16, 128 MiB
__device__ __align__(16) __half g_WvTh[(size_t)NVAL*KVC];   // Wv^T fp16 [n][k]

// ---------------- helpers ----------------
__device__ __forceinline__ float cvt_tf32(float x){
    float r; asm("cvt.rna.tf32.f32 %0, %1;" : "=f"(r) : "f"(x)); return r;
}
__device__ __forceinline__ uint32_t smem_u32(const void* p){
    uint32_t a;
    asm("{ .reg .u64 t; cvta.to.shared.u64 t, %1; cvt.u32.u64 %0, t; }" : "=r"(a) : "l"(p));
    return a;
}
__device__ __forceinline__ void cp16(uint32_t dst, const void* src){
    asm volatile("cp.async.cg.shared.global [%0], [%1], 16;" :: "r"(dst), "l"(src) : "memory");
}
__device__ __forceinline__ void ldm_x4(uint32_t a, uint32_t r[4]){
    asm volatile("ldmatrix.sync.aligned.m8n8.x4.shared.b16 {%0,%1,%2,%3}, [%4];"
                 : "=r"(r[0]), "=r"(r[1]), "=r"(r[2]), "=r"(r[3]) : "r"(a));
}
__device__ __forceinline__ void mma_f16(float c[4], const uint32_t a[4],
                                        uint32_t b0, uint32_t b1){
    asm volatile(
        "mma.sync.aligned.m16n8k16.row.col.f32.f16.f16.f32 "
        "{%0,%1,%2,%3},{%4,%5,%6,%7},{%8,%9},{%0,%1,%2,%3};\n"
        : "+f"(c[0]), "+f"(c[1]), "+f"(c[2]), "+f"(c[3])
        : "r"(a[0]), "r"(a[1]), "r"(a[2]), "r"(a[3]), "r"(b0), "r"(b1));
}
// m16n8k8 tf32 for the small logits GEMM
__device__ __forceinline__ void mma_tf32(float c[4],
                                         uint32_t a0, uint32_t a1, uint32_t a2, uint32_t a3,
                                         uint32_t b0, uint32_t b1){
    asm volatile(
        "mma.sync.aligned.m16n8k8.row.col.f32.tf32.tf32.f32 "
        "{%0,%1,%2,%3},{%4,%5,%6,%7},{%8,%9},{%0,%1,%2,%3};\n"
        : "+f"(c[0]), "+f"(c[1]), "+f"(c[2]), "+f"(c[3])
        : "r"(a0), "r"(a1), "r"(a2), "r"(a3), "r"(b0), "r"(b1));
}
__device__ __forceinline__ float fast_tanh(float x){
    x = fminf(fmaxf(x, -15.f), 15.f);
    float e = __expf(2.0f * x);
    return __fdividef(e - 1.0f, e + 1.0f);
}

// ---------------- kernel 0: transpose+convert Wv [512,1024] -> g_WvTh [1024,512] ----
__global__ void transpose_wv(const float* __restrict__ Wv){
    __shared__ float t[32][33];
    int n0 = blockIdx.x * 32, k0 = blockIdx.y * 32;
    int tx = threadIdx.x, ty = threadIdx.y;           // 32 x 8
    #pragma unroll
    for (int i = 0; i < 4; i++)
        t[ty + 8*i][tx] = Wv[(size_t)(k0 + ty + 8*i)*NVAL + n0 + tx];
    __syncthreads();
    #pragma unroll
    for (int i = 0; i < 4; i++)
        g_WvTh[(size_t)(n0 + ty + 8*i)*KVC + k0 + tx] = __float2half_rn(t[tx][ty + 8*i]);
}

// ---------------- kernel 1: fold query into W_k / b_k ----------------
__global__ void fold_q(const float* __restrict__ Wk, const float* __restrict__ bk,
                       const float* __restrict__ q){
    int n = blockIdx.x;
    __shared__ float qs[HD];
    if (threadIdx.x < HD) qs[threadIdx.x] = q[n*HD + threadIdx.x];
    __syncthreads();
    for (int c = threadIdx.x; c < KVC; c += blockDim.x){
        float s = 0.f;
        #pragma unroll 8
        for (int d = 0; d < HD; d++) s += Wk[(size_t)c*NVAL + n*HD + d] * qs[d];
        g_Wq[c*NH + n] = s;
    }
    if (threadIdx.x == 0){
        float s = 0.f;
        for (int d = 0; d < HD; d++) s += bk[n*HD + d] * qs[d];
        g_qb[n] = s;
    }
}

// ---------------- kernel 2: logits GEMM + x->fp16 conversion ----------------
__global__ __launch_bounds__(256) void logits_gemm(const float* __restrict__ x){
    __shared__ float As[128][68];
    __shared__ float Bs[64][24];
    int tid  = threadIdx.x;
    int wid  = tid >> 5, lane = tid & 31;
    int g    = lane >> 2, tq = lane & 3;
    int bm0  = blockIdx.x * 128;

    float acc[2][4] = {};

    for (int kt = 0; kt < KVC/64; kt++){
        int k0 = kt * 64;
        #pragma unroll
        for (int i = 0; i < 8; i++){
            int idx = tid + 256*i;
            int row = idx >> 4, c4 = (idx & 15) * 4;
            float4 v = *reinterpret_cast<const float4*>(x + (size_t)(bm0+row)*KVC + k0 + c4);
            __half2 h0 = __floats2half2_rn(v.x, v.y);
            __half2 h1 = __floats2half2_rn(v.z, v.w);
            uint2 u;
            u.x = *reinterpret_cast<uint32_t*>(&h0);
            u.y = *reinterpret_cast<uint32_t*>(&h1);
            *reinterpret_cast<uint2*>(&g_xh[(size_t)(bm0+row)*KVC + k0 + c4]) = u;
            float* d = &As[row][c4];
            d[0]=cvt_tf32(v.x); d[1]=cvt_tf32(v.y); d[2]=cvt_tf32(v.z); d[3]=cvt_tf32(v.w);
        }
        {
            int k = tid >> 2, n4 = (tid & 3) * 4;
            float4 v = *reinterpret_cast<const float4*>(g_Wq + (k0+k)*NH + n4);
            float* d = &Bs[k][n4];
            d[0]=cvt_tf32(v.x); d[1]=cvt_tf32(v.y); d[2]=cvt_tf32(v.z); d[3]=cvt_tf32(v.w);
        }
        __syncthreads();
        #pragma unroll
        for (int ks = 0; ks < 8; ks++){
            int m = wid*16 + g;
            uint32_t a0 = __float_as_uint(As[m    ][ks*8 + tq    ]);
            uint32_t a1 = __float_as_uint(As[m + 8][ks*8 + tq    ]);
            uint32_t a2 = __float_as_uint(As[m    ][ks*8 + tq + 4]);
            uint32_t a3 = __float_as_uint(As[m + 8][ks*8 + tq + 4]);
            #pragma unroll
            for (int ni = 0; ni < 2; ni++){
                uint32_t b0 = __float_as_uint(Bs[ks*8 + tq    ][ni*8 + g]);
                uint32_t b1 = __float_as_uint(Bs[ks*8 + tq + 4][ni*8 + g]);
                mma_tf32(acc[ni], a0,a1,a2,a3, b0,b1);
            }
        }
        __syncthreads();
    }
    #pragma unroll
    for (int ni = 0; ni < 2; ni++){
        #pragma unroll
        for (int r = 0; r < 4; r++){
            int row  = bm0 + wid*16 + g + ((r >= 2) ? 8 : 0);
            int head = ni*8 + 2*tq + (r & 1);
            int b = row >> 12, s = row & 4095;
            g_logits[(size_t)(b*NH + head)*HWSZ + s] = acc[ni][r] + g_qb[head];
        }
    }
}

// ---------------- kernel 3: softmax stats ----------------
__global__ void softmax_stats(){
    __shared__ float sm[256];
    int row = blockIdx.x, tid = threadIdx.x;
    const float* lp = g_logits + (size_t)row * HWSZ;
    float m = -1e30f;
    for (int i = tid; i < HWSZ; i += 256) m = fmaxf(m, lp[i]);
    sm[tid] = m; __syncthreads();
    for (int o = 128; o > 0; o >>= 1){
        if (tid < o) sm[tid] = fmaxf(sm[tid], sm[tid+o]);
        __syncthreads();
    }
    float mrow = sm[0];
    __syncthreads();
    float s = 0.f;
    for (int i = tid; i < HWSZ; i += 256) s += __expf(lp[i] - mrow);
    sm[tid] = s; __syncthreads();
    for (int o = 128; o > 0; o >>= 1){
        if (tid < o) sm[tid] += sm[tid+o];
        __syncthreads();
    }
    if (tid == 0){ g_mx[row] = mrow; g_inv[row] = 1.0f / sm[0]; }
}

// ---------------- kernel 4: fp16 value GEMM + fused epilogue ----------
// BM=128 x BN=128 tile, 8 warps (2x4), warp tile 64x32, BK=64, 3-stage cp.async
__global__ void __launch_bounds__(256, 2) value_f16(const float* __restrict__ bv){
    extern __shared__ char smc[];
    float* smf = (float*)smc;
    uint32_t sb = smem_u32(smc);
    int tid = threadIdx.x;
    int wid = tid >> 5, lane = tid & 31;
    int wm  = wid >> 2, wn = wid & 3;       // 2 x 4 warp grid, warp tile 64x32
    int bn0 = blockIdx.x * BN;
    int mt  = blockIdx.y;
    int bm0 = mt * BM;
    int g   = lane >> 2, tq = lane & 3;

    if (tid < BN) smf[(OFF_BV>>2) + tid] = bv[bn0 + tid];

    // cp.async mapping: per thread 4 consecutive 16B granules (64B) of one row
    int row = tid >> 1;
    int gq  = (tid & 1) * 4;
    const __half* srcA = g_xh   + (size_t)(bm0 + row)*KVC + gq*8;
    const __half* srcB = g_WvTh + (size_t)(bn0 + row)*KVC + gq*8;
    uint32_t dstA = sb + row*ROWB + gq*16;
    uint32_t dstB = sb + A_BYTES + row*ROWB + gq*16;

    #define LOAD_STAGE(kt) do{ \
        uint32_t so = (uint32_t)((kt) % 3) * STAGE_B; \
        int ko = (kt) * BK; \
        cp16(dstA + so,      srcA + ko); \
        cp16(dstA + so + 16, srcA + ko + 8); \
        cp16(dstA + so + 32, srcA + ko + 16); \
        cp16(dstA + so + 48, srcA + ko + 24); \
        cp16(dstB + so,      srcB + ko); \
        cp16(dstB + so + 16, srcB + ko + 8); \
        cp16(dstB + so + 32, srcB + ko + 16); \
        cp16(dstB + so + 48, srcB + ko + 24); \
    } while(0)

    LOAD_STAGE(0);
    asm volatile("cp.async.commit_group;" ::: "memory");
    LOAD_STAGE(1);
    asm volatile("cp.async.commit_group;" ::: "memory");

    // precompute softmax weights for this thread's 8 accumulator rows
    // (overlaps with cp.async prologue; removes LDG+exp from the epilogue)
    int head = (bn0 + wn*32) >> 6;           // warp's 32 cols lie within one head
    float wgt[8];
    #pragma unroll
    for (int mi = 0; mi < 4; mi++){
        #pragma unroll
        for (int rg = 0; rg < 2; rg++){
            int p  = bm0 + wm*64 + mi*16 + g + rg*8;
            int b  = p >> 12, s = p & 4095;
            int bh = b*NH + head;
            wgt[mi*2+rg] = __expf(g_logits[((size_t)bh << 12) + s] - g_mx[bh]) * g_inv[bh];
        }
    }

    float acc[4][4][4] = {};                 // [mi][ni][r]
    int lrow = lane & 15, lhi = lane >> 4;

    for (int kt = 0; kt < NCHUNK; kt++){
        asm volatile("cp.async.wait_group 1;" ::: "memory");
        __syncthreads();
        if (kt + 2 < NCHUNK) LOAD_STAGE(kt + 2);
        asm volatile("cp.async.commit_group;" ::: "memory");

        uint32_t so = (uint32_t)(kt % 3) * STAGE_B;
        uint32_t Ab = sb + so + (wm*64 + lrow)*ROWB;
        uint32_t Bb = sb + so + A_BYTES + (wn*32 + lrow)*ROWB;

        #pragma unroll
        for (int ks = 0; ks < 4; ks++){
            uint32_t gsel = (ks*2 + lhi) * 16;
            uint32_t a[4][4];
            #pragma unroll
            for (int mi = 0; mi < 4; mi++)
                ldm_x4(Ab + mi*16*ROWB + gsel, a[mi]);
            uint32_t b[4][2];
            #pragma unroll
            for (int np = 0; np < 2; np++){
                uint32_t r[4];
                ldm_x4(Bb + np*16*ROWB + gsel, r);
                b[2*np  ][0] = r[0]; b[2*np  ][1] = r[2];
                b[2*np+1][0] = r[1]; b[2*np+1][1] = r[3];
            }
            #pragma unroll
            for (int mi = 0; mi < 4; mi++)
                #pragma unroll
                for (int ni = 0; ni < 4; ni++)
                    mma_f16(acc[mi][ni], a[mi], b[ni][0], b[ni][1]);
        }
    }
    __syncthreads();

    // ---- epilogue: tanh + attention weight + reduce over 128 tile rows ----
    float* bvs = smf + (OFF_BV >> 2);
    float colsum[8] = {};
    #pragma unroll
    for (int mi = 0; mi < 4; mi++){
        #pragma unroll
        for (int rg = 0; rg < 2; rg++){
            float w = wgt[mi*2+rg];
            #pragma unroll
            for (int ni = 0; ni < 4; ni++){
                #pragma unroll
                for (int c01 = 0; c01 < 2; c01++){
                    int j = wn*32 + ni*8 + 2*tq + c01;
                    float t = fast_tanh(acc[mi][ni][rg*2 + c01] + bvs[j]);
                    colsum[ni*2 + c01] += w * t;
                }
            }
        }
    }
    #pragma unroll
    for (int i = 0; i < 8; i++){
        colsum[i] += __shfl_xor_sync(0xffffffffu, colsum[i], 16);
        colsum[i] += __shfl_xor_sync(0xffffffffu, colsum[i], 8);
        colsum[i] += __shfl_xor_sync(0xffffffffu, colsum[i], 4);
    }
    float* red = smf + (OFF_RED >> 2);       // [8 warps][32 cols]
    if (lane < 4){
        #pragma unroll
        for (int ni = 0; ni < 4; ni++)
            #pragma unroll
            for (int c01 = 0; c01 < 2; c01++)
                red[(wm*4 + wn)*32 + ni*8 + 2*tq + c01] = colsum[ni*2 + c01];
    }
    __syncthreads();
    if (tid < BN){
        float v = red[(tid >> 5)*32 + (tid & 31)] + red[(4 + (tid >> 5))*32 + (tid & 31)];
        g_partial[(size_t)mt*NVAL + bn0 + tid] = v;   // unique writer -> deterministic
    }
}

// ---------------- kernel 5: reduce partials ----------------
__global__ void reduce_out(float* __restrict__ out){
    int o = blockIdx.x * 256 + threadIdx.x;   // 32768 outputs [b][n][v]
    int b = o >> 10, j = o & 1023;
    float s = 0.f;
    #pragma unroll
    for (int i = 0; i < 32; i++)
        s += g_partial[(size_t)(b*32 + i)*NVAL + j];
    out[o] = s;
}

// ---------------- launch ----------------
extern "C" void kernel_launch(void* const* d_in, const int* in_sizes, int n_in,
                              void* d_out, int out_size){
    const float* kv = (const float*)d_in[0];
    const float* Wk = (const float*)d_in[1];
    const float* bk = (const float*)d_in[2];
    const float* Wv = (const float*)d_in[3];
    const float* bv = (const float*)d_in[4];
    const float* q  = (const float*)d_in[5];
    float* out = (float*)d_out;

    static bool attr_done = false;
    if (!attr_done){
        cudaFuncSetAttribute(value_f16, cudaFuncAttributeMaxDynamicSharedMemorySize, SMEMB);
        attr_done = true;
    }

    transpose_wv<<<dim3(NVAL/32, KVC/32), dim3(32, 8)>>>(Wv);
    fold_q<<<NH, 128>>>(Wk, bk, q);
    logits_gemm<<<MTOT/128, 256>>>(kv);
    softmax_stats<<<NB*NH, 256>>>();
    value_f16<<<dim3(NVAL/BN, MTOT/BM), 256, SMEMB>>>(bv);
    reduce_out<<<(NB*NVAL)/256, 256>>>(out);
}

// round 7
// speedup vs baseline: 1.2242x; 1.1040x over previous
#include <cuda_runtime.h>
#include <cuda_fp16.h>
#include <cstdint>

// Problem constants
#define KVC   512
#define NH    16
#define HD    64
#define HWSZ  4096
#define NB    32
#define MTOT  (NB*HWSZ)     // 131072 pixels
#define NVAL  1024          // NH*HD value columns

// value-kernel tiles (fp16 mma): BM=128 x BN=256, 512 threads, warp tile 64x32
#define BM      128
#define BN      256
#define BK      32
#define NCHUNK  (KVC/BK)    // 16
#define NSTAGE  4
#define ROWB    80          // 32 fp16 = 64B + 16B pad (conflict-free ldmatrix)
#define A_BYTES (BM*ROWB)              // 10240
#define STAGE_B ((BM+BN)*ROWB)         // 30720
#define OFF_RED (NSTAGE*STAGE_B)       // red[16][32] floats = 2048 B
#define OFF_BV  (OFF_RED + 2048)       // bv tile [256] = 1024 B
#define SMEMB   (OFF_BV + BN*4)        // 125952 B -> 1 CTA/SM (16 warps)

// ---------------- device scratch ----------------
__device__ __align__(16) float g_Wq[KVC*NH];
__device__ float g_qb[NH];
__device__ float g_logits[(size_t)(NB*NH)*HWSZ];      // [b*16+n][s], 8 MiB
__device__ float g_mx[NB*NH];
__device__ float g_inv[NB*NH];
__device__ __align__(16) float g_partial[(size_t)(MTOT/BM)*NVAL];
__device__ __align__(16) __half g_xh[(size_t)MTOT*KVC];     // x in fp16, 128 MiB
__device__ __align__(16) __half g_WvTh[(size_t)NVAL*KVC];   // Wv^T fp16 [n][k]

// ---------------- helpers ----------------
__device__ __forceinline__ float cvt_tf32(float x){
    float r; asm("cvt.rna.tf32.f32 %0, %1;" : "=f"(r) : "f"(x)); return r;
}
__device__ __forceinline__ uint32_t smem_u32(const void* p){
    uint32_t a;
    asm("{ .reg .u64 t; cvta.to.shared.u64 t, %1; cvt.u32.u64 %0, t; }" : "=r"(a) : "l"(p));
    return a;
}
__device__ __forceinline__ void cp16(uint32_t dst, const void* src){
    asm volatile("cp.async.cg.shared.global [%0], [%1], 16;" :: "r"(dst), "l"(src) : "memory");
}
__device__ __forceinline__ void ldm_x4(uint32_t a, uint32_t r[4]){
    asm volatile("ldmatrix.sync.aligned.m8n8.x4.shared.b16 {%0,%1,%2,%3}, [%4];"
                 : "=r"(r[0]), "=r"(r[1]), "=r"(r[2]), "=r"(r[3]) : "r"(a));
}
__device__ __forceinline__ void mma_f16(float c[4], const uint32_t a[4],
                                        uint32_t b0, uint32_t b1){
    asm volatile(
        "mma.sync.aligned.m16n8k16.row.col.f32.f16.f16.f32 "
        "{%0,%1,%2,%3},{%4,%5,%6,%7},{%8,%9},{%0,%1,%2,%3};\n"
        : "+f"(c[0]), "+f"(c[1]), "+f"(c[2]), "+f"(c[3])
        : "r"(a[0]), "r"(a[1]), "r"(a[2]), "r"(a[3]), "r"(b0), "r"(b1));
}
// m16n8k8 tf32 for the small logits GEMM
__device__ __forceinline__ void mma_tf32(float c[4],
                                         uint32_t a0, uint32_t a1, uint32_t a2, uint32_t a3,
                                         uint32_t b0, uint32_t b1){
    asm volatile(
        "mma.sync.aligned.m16n8k8.row.col.f32.tf32.tf32.f32 "
        "{%0,%1,%2,%3},{%4,%5,%6,%7},{%8,%9},{%0,%1,%2,%3};\n"
        : "+f"(c[0]), "+f"(c[1]), "+f"(c[2]), "+f"(c[3])
        : "r"(a0), "r"(a1), "r"(a2), "r"(a3), "r"(b0), "r"(b1));
}
__device__ __forceinline__ float fast_tanh(float x){
    x = fminf(fmaxf(x, -15.f), 15.f);
    float e = __expf(2.0f * x);
    return __fdividef(e - 1.0f, e + 1.0f);
}

// ---------------- kernel 0: transpose+convert Wv [512,1024] -> g_WvTh [1024,512] ----
__global__ void transpose_wv(const float* __restrict__ Wv){
    __shared__ float t[32][33];
    int n0 = blockIdx.x * 32, k0 = blockIdx.y * 32;
    int tx = threadIdx.x, ty = threadIdx.y;           // 32 x 8
    #pragma unroll
    for (int i = 0; i < 4; i++)
        t[ty + 8*i][tx] = Wv[(size_t)(k0 + ty + 8*i)*NVAL + n0 + tx];
    __syncthreads();
    #pragma unroll
    for (int i = 0; i < 4; i++)
        g_WvTh[(size_t)(n0 + ty + 8*i)*KVC + k0 + tx] = __float2half_rn(t[tx][ty + 8*i]);
}

// ---------------- kernel 1: fold query into W_k / b_k ----------------
__global__ void fold_q(const float* __restrict__ Wk, const float* __restrict__ bk,
                       const float* __restrict__ q){
    int n = blockIdx.x;
    __shared__ float qs[HD];
    if (threadIdx.x < HD) qs[threadIdx.x] = q[n*HD + threadIdx.x];
    __syncthreads();
    for (int c = threadIdx.x; c < KVC; c += blockDim.x){
        float s = 0.f;
        #pragma unroll 8
        for (int d = 0; d < HD; d++) s += Wk[(size_t)c*NVAL + n*HD + d] * qs[d];
        g_Wq[c*NH + n] = s;
    }
    if (threadIdx.x == 0){
        float s = 0.f;
        for (int d = 0; d < HD; d++) s += bk[n*HD + d] * qs[d];
        g_qb[n] = s;
    }
}

// ---------------- kernel 2: logits GEMM + x->fp16 conversion ----------------
__global__ __launch_bounds__(256) void logits_gemm(const float* __restrict__ x){
    __shared__ float As[128][68];
    __shared__ float Bs[64][24];
    int tid  = threadIdx.x;
    int wid  = tid >> 5, lane = tid & 31;
    int g    = lane >> 2, tq = lane & 3;
    int bm0  = blockIdx.x * 128;

    float acc[2][4] = {};

    for (int kt = 0; kt < KVC/64; kt++){
        int k0 = kt * 64;
        #pragma unroll
        for (int i = 0; i < 8; i++){
            int idx = tid + 256*i;
            int row = idx >> 4, c4 = (idx & 15) * 4;
            float4 v = *reinterpret_cast<const float4*>(x + (size_t)(bm0+row)*KVC + k0 + c4);
            __half2 h0 = __floats2half2_rn(v.x, v.y);
            __half2 h1 = __floats2half2_rn(v.z, v.w);
            uint2 u;
            u.x = *reinterpret_cast<uint32_t*>(&h0);
            u.y = *reinterpret_cast<uint32_t*>(&h1);
            *reinterpret_cast<uint2*>(&g_xh[(size_t)(bm0+row)*KVC + k0 + c4]) = u;
            float* d = &As[row][c4];
            d[0]=cvt_tf32(v.x); d[1]=cvt_tf32(v.y); d[2]=cvt_tf32(v.z); d[3]=cvt_tf32(v.w);
        }
        {
            int k = tid >> 2, n4 = (tid & 3) * 4;
            float4 v = *reinterpret_cast<const float4*>(g_Wq + (k0+k)*NH + n4);
            float* d = &Bs[k][n4];
            d[0]=cvt_tf32(v.x); d[1]=cvt_tf32(v.y); d[2]=cvt_tf32(v.z); d[3]=cvt_tf32(v.w);
        }
        __syncthreads();
        #pragma unroll
        for (int ks = 0; ks < 8; ks++){
            int m = wid*16 + g;
            uint32_t a0 = __float_as_uint(As[m    ][ks*8 + tq    ]);
            uint32_t a1 = __float_as_uint(As[m + 8][ks*8 + tq    ]);
            uint32_t a2 = __float_as_uint(As[m    ][ks*8 + tq + 4]);
            uint32_t a3 = __float_as_uint(As[m + 8][ks*8 + tq + 4]);
            #pragma unroll
            for (int ni = 0; ni < 2; ni++){
                uint32_t b0 = __float_as_uint(Bs[ks*8 + tq    ][ni*8 + g]);
                uint32_t b1 = __float_as_uint(Bs[ks*8 + tq + 4][ni*8 + g]);
                mma_tf32(acc[ni], a0,a1,a2,a3, b0,b1);
            }
        }
        __syncthreads();
    }
    #pragma unroll
    for (int ni = 0; ni < 2; ni++){
        #pragma unroll
        for (int r = 0; r < 4; r++){
            int row  = bm0 + wid*16 + g + ((r >= 2) ? 8 : 0);
            int head = ni*8 + 2*tq + (r & 1);
            int b = row >> 12, s = row & 4095;
            g_logits[(size_t)(b*NH + head)*HWSZ + s] = acc[ni][r] + g_qb[head];
        }
    }
}

// ---------------- kernel 3: softmax stats ----------------
__global__ void softmax_stats(){
    __shared__ float sm[256];
    int row = blockIdx.x, tid = threadIdx.x;
    const float* lp = g_logits + (size_t)row * HWSZ;
    float m = -1e30f;
    for (int i = tid; i < HWSZ; i += 256) m = fmaxf(m, lp[i]);
    sm[tid] = m; __syncthreads();
    for (int o = 128; o > 0; o >>= 1){
        if (tid < o) sm[tid] = fmaxf(sm[tid], sm[tid+o]);
        __syncthreads();
    }
    float mrow = sm[0];
    __syncthreads();
    float s = 0.f;
    for (int i = tid; i < HWSZ; i += 256) s += __expf(lp[i] - mrow);
    sm[tid] = s; __syncthreads();
    for (int o = 128; o > 0; o >>= 1){
        if (tid < o) sm[tid] += sm[tid+o];
        __syncthreads();
    }
    if (tid == 0){ g_mx[row] = mrow; g_inv[row] = 1.0f / sm[0]; }
}

// ---------------- kernel 4: fp16 value GEMM + fused epilogue ----------
// BM=128 x BN=256, 512 threads (16 warps, 2x8), warp tile 64x32, 4-stage cp.async
__global__ void __launch_bounds__(512, 1) value_f16(const float* __restrict__ bv){
    extern __shared__ char smc[];
    float* smf = (float*)smc;
    uint32_t sb = smem_u32(smc);
    int tid = threadIdx.x;
    int wid = tid >> 5, lane = tid & 31;
    int wm  = wid >> 3, wn = wid & 7;       // 2 x 8 warp grid, warp tile 64x32
    int bn0 = blockIdx.x * BN;
    int mt  = blockIdx.y;
    int bm0 = mt * BM;
    int g   = lane >> 2, tq = lane & 3;

    if (tid < BN) smf[(OFF_BV>>2) + tid] = bv[bn0 + tid];

    // cp.async mapping: A: 1 granule/thread (512 = 128 rows x 4); B: 2 granules
    int rowA = tid >> 2, grA = tid & 3;
    int rowB = tid >> 1, grB = (tid & 1) * 2;
    const __half* srcA = g_xh   + (size_t)(bm0 + rowA)*KVC + grA*8;
    const __half* srcB = g_WvTh + (size_t)(bn0 + rowB)*KVC + grB*8;
    uint32_t dstA = sb + rowA*ROWB + grA*16;
    uint32_t dstB = sb + A_BYTES + rowB*ROWB + grB*16;

    #define LOAD_STAGE(kt) do{ \
        uint32_t so = (uint32_t)((kt) % NSTAGE) * STAGE_B; \
        int ko = (kt) * BK; \
        cp16(dstA + so,      srcA + ko); \
        cp16(dstB + so,      srcB + ko); \
        cp16(dstB + so + 16, srcB + ko + 8); \
    } while(0)

    LOAD_STAGE(0);
    asm volatile("cp.async.commit_group;" ::: "memory");
    LOAD_STAGE(1);
    asm volatile("cp.async.commit_group;" ::: "memory");
    LOAD_STAGE(2);
    asm volatile("cp.async.commit_group;" ::: "memory");

    // precompute softmax weights for this thread's 8 accumulator rows
    // (overlaps with the cp.async prologue; epilogue becomes pure register math)
    int head = (bn0 + wn*32) >> 6;           // warp's 32 cols lie within one head
    float wgt[8];
    #pragma unroll
    for (int mi = 0; mi < 4; mi++){
        #pragma unroll
        for (int rg = 0; rg < 2; rg++){
            int p  = bm0 + wm*64 + mi*16 + g + rg*8;
            int b  = p >> 12, s = p & 4095;
            int bh = b*NH + head;
            wgt[mi*2+rg] = __expf(g_logits[((size_t)bh << 12) + s] - g_mx[bh]) * g_inv[bh];
        }
    }

    float acc[4][4][4] = {};                 // [mi][ni][r]
    int lrow = lane & 15, lhi = lane >> 4;

    for (int kt = 0; kt < NCHUNK; kt++){
        asm volatile("cp.async.wait_group 2;" ::: "memory");
        __syncthreads();
        if (kt + 3 < NCHUNK) LOAD_STAGE(kt + 3);
        asm volatile("cp.async.commit_group;" ::: "memory");

        uint32_t so = (uint32_t)(kt % NSTAGE) * STAGE_B;
        uint32_t Ab = sb + so + (wm*64 + lrow)*ROWB;
        uint32_t Bb = sb + so + A_BYTES + (wn*32 + lrow)*ROWB;

        #pragma unroll
        for (int ks = 0; ks < 2; ks++){
            uint32_t gsel = (ks*2 + lhi) * 16;
            uint32_t a[4][4];
            #pragma unroll
            for (int mi = 0; mi < 4; mi++)
                ldm_x4(Ab + mi*16*ROWB + gsel, a[mi]);
            uint32_t b[4][2];
            #pragma unroll
            for (int np = 0; np < 2; np++){
                uint32_t r[4];
                ldm_x4(Bb + np*16*ROWB + gsel, r);
                b[2*np  ][0] = r[0]; b[2*np  ][1] = r[2];
                b[2*np+1][0] = r[1]; b[2*np+1][1] = r[3];
            }
            #pragma unroll
            for (int mi = 0; mi < 4; mi++)
                #pragma unroll
                for (int ni = 0; ni < 4; ni++)
                    mma_f16(acc[mi][ni], a[mi], b[ni][0], b[ni][1]);
        }
    }

    // ---- epilogue: tanh + attention weight + reduce over 128 tile rows ----
    float* bvs = smf + (OFF_BV >> 2);
    float colsum[8] = {};
    #pragma unroll
    for (int mi = 0; mi < 4; mi++){
        #pragma unroll
        for (int rg = 0; rg < 2; rg++){
            float w = wgt[mi*2+rg];
            #pragma unroll
            for (int ni = 0; ni < 4; ni++){
                #pragma unroll
                for (int c01 = 0; c01 < 2; c01++){
                    int j = wn*32 + ni*8 + 2*tq + c01;
                    float t = fast_tanh(acc[mi][ni][rg*2 + c01] + bvs[j]);
                    colsum[ni*2 + c01] += w * t;
                }
            }
        }
    }
    #pragma unroll
    for (int i = 0; i < 8; i++){
        colsum[i] += __shfl_xor_sync(0xffffffffu, colsum[i], 16);
        colsum[i] += __shfl_xor_sync(0xffffffffu, colsum[i], 8);
        colsum[i] += __shfl_xor_sync(0xffffffffu, colsum[i], 4);
    }
    float* red = smf + (OFF_RED >> 2);       // [16 warps][32 cols]
    if (lane < 4){
        #pragma unroll
        for (int ni = 0; ni < 4; ni++)
            #pragma unroll
            for (int c01 = 0; c01 < 2; c01++)
                red[(wm*8 + wn)*32 + ni*8 + 2*tq + c01] = colsum[ni*2 + c01];
    }
    __syncthreads();
    if (tid < BN){
        float v = red[(tid >> 5)*32 + (tid & 31)] + red[(8 + (tid >> 5))*32 + (tid & 31)];
        g_partial[(size_t)mt*NVAL + bn0 + tid] = v;   // unique writer -> deterministic
    }
}

// ---------------- kernel 5: reduce partials ----------------
__global__ void reduce_out(float* __restrict__ out){
    int o = blockIdx.x * 256 + threadIdx.x;   // 32768 outputs [b][n][v]
    int b = o >> 10, j = o & 1023;
    float s = 0.f;
    #pragma unroll
    for (int i = 0; i < 32; i++)
        s += g_partial[(size_t)(b*32 + i)*NVAL + j];
    out[o] = s;
}

// ---------------- launch ----------------
extern "C" void kernel_launch(void* const* d_in, const int* in_sizes, int n_in,
                              void* d_out, int out_size){
    const float* kv = (const float*)d_in[0];
    const float* Wk = (const float*)d_in[1];
    const float* bk = (const float*)d_in[2];
    const float* Wv = (const float*)d_in[3];
    const float* bv = (const float*)d_in[4];
    const float* q  = (const float*)d_in[5];
    float* out = (float*)d_out;

    static bool attr_done = false;
    if (!attr_done){
        cudaFuncSetAttribute(value_f16, cudaFuncAttributeMaxDynamicSharedMemorySize, SMEMB);
        attr_done = true;
    }

    transpose_wv<<<dim3(NVAL/32, KVC/32), dim3(32, 8)>>>(Wv);
    fold_q<<<NH, 128>>>(Wk, bk, q);
    logits_gemm<<<MTOT/128, 256>>>(kv);
    softmax_stats<<<NB*NH, 256>>>();
    value_f16<<<dim3(NVAL/BN, MTOT/BM), 512, SMEMB>>>(bv);
    reduce_out<<<(NB*NVAL)/256, 256>>>(out);
}